// round 2
// baseline (speedup 1.0000x reference)
#include <cuda_runtime.h>
#include <cuda_bf16.h>
#include <cstdint>
#include <math.h>

// Shapes: text[256,512] f32, clip[256,512] f32, concept[256,32,512] f32,
// frame[256,64,512] f32, logit_scale scalar, out[256,256] f32.
// Big GEMM S[8192,16384] = nc @ nf^T (bf16, f32 acc) with fused
// max-over-64-frames / mean-over-32-tokens epilogue + fp32 g_sim.
// NOTE: harness PTX target is compute_103 (no 'a') -> no tcgen05/TMEM.
// Use mma.sync.m16n8k16 (HMMA) + cp.async pipeline instead.

#define D_K     512
#define A_ROWS  8192
#define B_ROWS  16384
#define TM      128
#define TN      128
#define KC      64            // k-chunk: 64 bf16 = 128 B per row
#define NCH     8             // 512 / 64
#define MT      64            // 8192 / 128
#define NT      128           // 16384 / 128
#define AIMG    16384         // 128 rows * 128 B
#define BIMG    16384
#define STAGE   32768
#define NSTAGES 3
#define SMEM_DYN (NSTAGES * STAGE)

// Packed, pre-swizzled (SW128-style XOR) bf16 operand images:
//   g_ncp: [chunk(8)][mtile(64)][16384 B]
//   g_nfp: [chunk(8)][ntile(128)][16384 B]
__device__ __align__(256) unsigned char g_ncp[(size_t)NCH * MT * AIMG];
__device__ __align__(256) unsigned char g_nfp[(size_t)NCH * NT * BIMG];

// ---------------------------------------------------------------------------
__device__ __forceinline__ uint32_t smem_u32(const void* p) {
    uint32_t a;
    asm("{ .reg .u64 t; cvta.to.shared.u64 t, %1; cvt.u32.u64 %0, t; }"
        : "=r"(a) : "l"(p));
    return a;
}

__device__ __forceinline__ void cp_async16(uint32_t dst, const void* src) {
    asm volatile("cp.async.cg.shared.global [%0], [%1], 16;"
                 :: "r"(dst), "l"(src) : "memory");
}
__device__ __forceinline__ void cp_commit() {
    asm volatile("cp.async.commit_group;" ::: "memory");
}
template <int N>
__device__ __forceinline__ void cp_wait() {
    asm volatile("cp.async.wait_group %0;" :: "n"(N) : "memory");
}

__device__ __forceinline__ void ldm_x4(uint32_t* r, uint32_t addr) {
    asm volatile("ldmatrix.sync.aligned.m8n8.x4.shared.b16 {%0,%1,%2,%3}, [%4];"
                 : "=r"(r[0]), "=r"(r[1]), "=r"(r[2]), "=r"(r[3]) : "r"(addr));
}

__device__ __forceinline__ void mma16816(float* c, const uint32_t* a,
                                         uint32_t b0, uint32_t b1) {
    asm volatile(
        "mma.sync.aligned.m16n8k16.row.col.f32.bf16.bf16.f32 "
        "{%0,%1,%2,%3}, {%4,%5,%6,%7}, {%8,%9}, {%0,%1,%2,%3};"
        : "+f"(c[0]), "+f"(c[1]), "+f"(c[2]), "+f"(c[3])
        : "r"(a[0]), "r"(a[1]), "r"(a[2]), "r"(a[3]), "r"(b0), "r"(b1));
}

// ---------------------------------------------------------------------------
// Kernel 1: L2-normalize (fp32) -> bf16, write pre-swizzled packed tile images.
// One warp per row (512 f32).
// ---------------------------------------------------------------------------
__global__ __launch_bounds__(256) void prep_kernel(
    const float* __restrict__ concept_e, const float* __restrict__ frame_e) {
    int w = threadIdx.x >> 5;
    int lane = threadIdx.x & 31;
    int R = blockIdx.x * 8 + w;                 // 0 .. 24575

    const float* src;
    unsigned char* img;
    size_t chunk_stride;
    int rowin;
    if (R < A_ROWS) {
        src = concept_e + (size_t)R * D_K;
        img = g_ncp + (size_t)(R >> 7) * AIMG;   // mtile
        rowin = R & 127;
        chunk_stride = (size_t)MT * AIMG;
    } else {
        int Rf = R - A_ROWS;
        src = frame_e + (size_t)Rf * D_K;
        img = g_nfp + (size_t)(Rf >> 7) * BIMG;  // ntile
        rowin = Rf & 127;
        chunk_stride = (size_t)NT * BIMG;
    }

    float4 v[4];
    const float4* s4 = (const float4*)src;
#pragma unroll
    for (int i = 0; i < 4; i++) v[i] = s4[lane * 4 + i];

    float ss = 0.f;
#pragma unroll
    for (int i = 0; i < 4; i++)
        ss += v[i].x * v[i].x + v[i].y * v[i].y + v[i].z * v[i].z + v[i].w * v[i].w;
#pragma unroll
    for (int off = 16; off > 0; off >>= 1)
        ss += __shfl_xor_sync(0xffffffffu, ss, off);

    float inv = 1.0f / fmaxf(sqrtf(ss), 1e-12f);

    union { __nv_bfloat162 h[8]; uint4 q[2]; } u;
#pragma unroll
    for (int i = 0; i < 4; i++) {
        u.h[2 * i]     = __float22bfloat162_rn(make_float2(v[i].x * inv, v[i].y * inv));
        u.h[2 * i + 1] = __float22bfloat162_rn(make_float2(v[i].z * inv, v[i].w * inv));
    }

    int kbase = lane * 16;
#pragma unroll
    for (int uu = 0; uu < 2; uu++) {
        int kin = kbase + uu * 8;               // element index in [0,512)
        int chunk = kin >> 6;
        int off = rowin * 128 + (kin & 63) * 2; // bytes within tile image
        int swz = off ^ ((off >> 3) & 0x70);    // SW128-style XOR
        *(uint4*)(img + (size_t)chunk * chunk_stride + swz) = u.q[uu];
    }
}

// ---------------------------------------------------------------------------
// Kernel 2: HMMA GEMM tile (128x128, K=512) with cp.async 3-stage pipeline and
// fused max/mean epilogue + fp32 g_sim.
// Warp layout: 8 warps = 4 (M) x 2 (N); warp tile 32(m) x 64(n).
// warp == (1 token, 1 video) -> produces exactly one output element.
// ---------------------------------------------------------------------------
__global__ void __launch_bounds__(256, 2) gemm_kernel(
    const float* __restrict__ text, const float* __restrict__ clip,
    const float* __restrict__ lsc, float* __restrict__ out) {
    extern __shared__ unsigned char smem[];
    uint32_t sbase = smem_u32(smem);

    int tid = threadIdx.x, wid = tid >> 5, lane = tid & 31;
    int mtile = blockIdx.y, ntile = blockIdx.x;
    int wm = wid >> 1, wn = wid & 1;

    const unsigned char* asrc = g_ncp + (size_t)mtile * AIMG;
    const unsigned char* bsrc = g_nfp + (size_t)ntile * BIMG;
    const size_t ACS = (size_t)MT * AIMG;
    const size_t BCS = (size_t)NT * BIMG;

    // ---- per-lane ldmatrix address pre-computation (swizzle folded in) ----
    // A fragment rows: m = wm*32 + mt*16 + (lane & 15); k-half from bit4 of lane
    uint32_t Aoff[2], Axm[2];
#pragma unroll
    for (int mt = 0; mt < 2; mt++) {
        int row = wm * 32 + mt * 16 + (lane & 15);
        Aoff[mt] = row * 128;
        Axm[mt] = (row & 7) << 4;
    }
    uint32_t kA = (lane & 16);                  // +8 elements = +16 bytes

    // B fragment rows: n = wn*64 + bp*16 + (lane & 7) + ((lane & 16) ? 8 : 0)
    uint32_t Boff[4], Bxm[4];
#pragma unroll
    for (int bp = 0; bp < 4; bp++) {
        int row = wn * 64 + bp * 16 + (lane & 7) + ((lane & 16) ? 8 : 0);
        Boff[bp] = row * 128;
        Bxm[bp] = (row & 7) << 4;
    }
    uint32_t kB = (lane & 8) ? 16u : 0u;

    float acc[2][8][4];
#pragma unroll
    for (int i = 0; i < 2; i++)
#pragma unroll
        for (int j = 0; j < 8; j++)
#pragma unroll
            for (int k = 0; k < 4; k++) acc[i][j][k] = 0.f;

    // ---- prologue: prefetch NSTAGES chunks ----
#pragma unroll
    for (int c = 0; c < NSTAGES; c++) {
        uint32_t dst = sbase + c * STAGE;
#pragma unroll
        for (int j = 0; j < 8; j++) {
            uint32_t off = tid * 16 + j * 4096;
            const unsigned char* src = (j < 4)
                ? asrc + c * ACS + off
                : bsrc + c * BCS + (off - AIMG);
            cp_async16(dst + off, src);
        }
        cp_commit();
    }

    // ---- main loop over 8 K-chunks ----
#pragma unroll 1
    for (int c = 0; c < NCH; c++) {
        cp_wait<NSTAGES - 1>();
        __syncthreads();

        uint32_t sa = sbase + (c % NSTAGES) * STAGE;
        uint32_t sb = sa + AIMG;

#pragma unroll
        for (int ks = 0; ks < 4; ks++) {
            uint32_t kb = ks * 32;              // 16 elements * 2 B
            uint32_t a[2][4], b[4][4];
#pragma unroll
            for (int mt = 0; mt < 2; mt++)
                ldm_x4(a[mt], sa + Aoff[mt] + ((kb + kA) ^ Axm[mt]));
#pragma unroll
            for (int bp = 0; bp < 4; bp++)
                ldm_x4(b[bp], sb + Boff[bp] + ((kb + kB) ^ Bxm[bp]));
#pragma unroll
            for (int mt = 0; mt < 2; mt++)
#pragma unroll
                for (int bp = 0; bp < 4; bp++) {
                    mma16816(acc[mt][2 * bp],     a[mt], b[bp][0], b[bp][1]);
                    mma16816(acc[mt][2 * bp + 1], a[mt], b[bp][2], b[bp][3]);
                }
        }

        __syncthreads();
        if (c + NSTAGES < NCH) {
            int cn = c + NSTAGES;
            uint32_t dst = sbase + (cn % NSTAGES) * STAGE;
#pragma unroll
            for (int j = 0; j < 8; j++) {
                uint32_t off = tid * 16 + j * 4096;
                const unsigned char* src = (j < 4)
                    ? asrc + cn * ACS + off
                    : bsrc + cn * BCS + (off - AIMG);
                cp_async16(dst + off, src);
            }
            cp_commit();
        }
    }

    // ---- fused epilogue ----
    // lane holds rows m = mt*16 + (lane>>2) + 8h (h=0,1), cols 2 per acc frag.
    float rm[2][2];
#pragma unroll
    for (int mt = 0; mt < 2; mt++)
#pragma unroll
        for (int h = 0; h < 2; h++) {
            float m = -3.4e38f;
#pragma unroll
            for (int nt = 0; nt < 8; nt++)
                m = fmaxf(m, fmaxf(acc[mt][nt][2 * h], acc[mt][nt][2 * h + 1]));
            rm[mt][h] = m;
        }
    // max across the 4 lanes of each quad (same rows, different n-cols)
#pragma unroll
    for (int off = 1; off <= 2; off <<= 1) {
#pragma unroll
        for (int mt = 0; mt < 2; mt++)
#pragma unroll
            for (int h = 0; h < 2; h++)
                rm[mt][h] = fmaxf(rm[mt][h],
                                  __shfl_xor_sync(0xffffffffu, rm[mt][h], off));
    }
    // sum row-maxes over the token's 32 q-rows
    float s = rm[0][0] + rm[0][1] + rm[1][0] + rm[1][1];
#pragma unroll
    for (int off = 4; off <= 16; off <<= 1)
        s += __shfl_xor_sync(0xffffffffu, s, off);
    float mean = s * (1.0f / 32.0f);

    int t = mtile * 4 + wm;
    int v = ntile * 2 + wn;

    // fp32 g_sim dot
    const float4* tr = (const float4*)(text + (size_t)t * D_K);
    const float4* cr = (const float4*)(clip + (size_t)v * D_K);
    float g = 0.f;
#pragma unroll
    for (int j = 0; j < 4; j++) {
        float4 tv = tr[lane * 4 + j];
        float4 cv = cr[lane * 4 + j];
        g += tv.x * cv.x + tv.y * cv.y + tv.z * cv.z + tv.w * cv.w;
    }
#pragma unroll
    for (int off = 16; off > 0; off >>= 1)
        g += __shfl_xor_sync(0xffffffffu, g, off);

    if (lane == 0) {
        float scale = fminf(expf(lsc[0]), 100.0f);
        out[(size_t)t * 256 + v] = scale * (0.7f * g + 0.3f * mean);
    }
}

// ---------------------------------------------------------------------------
extern "C" void kernel_launch(void* const* d_in, const int* in_sizes, int n_in,
                              void* d_out, int out_size) {
    const float* text    = (const float*)d_in[0];
    const float* clip    = (const float*)d_in[1];
    const float* concept = (const float*)d_in[2];
    const float* frame   = (const float*)d_in[3];
    const float* lsc     = (const float*)d_in[4];
    float* out = (float*)d_out;

    prep_kernel<<<(A_ROWS + B_ROWS) / 8, 256>>>(concept, frame);

    cudaFuncSetAttribute(gemm_kernel, cudaFuncAttributeMaxDynamicSharedMemorySize,
                         SMEM_DYN);
    gemm_kernel<<<dim3(NT, MT), 256, SMEM_DYN>>>(text, clip, lsc, out);
}